// round 12
// baseline (speedup 1.0000x reference)
#include <cuda_runtime.h>
#include <cuda_bf16.h>
#include <math.h>
#include <stdint.h>

// ---------------- problem constants ----------------
#define Bn    128
#define TU    256
#define TBt   128
#define TPt   64
#define Hd    512
#define Ed    512
#define Vd    3000
#define VOOVd 3400
#define PTRd  32
#define XD    2080
#define G3H   1536
#define NEGV  (-1e20f)
#define MATT  (Bn*TU + Bn*TBt + Bn*TPt)   // 57344 merged attention rows
#define YATT  (MATT/128)                   // 448 attention y-blocks
#define YCPY  ((Bn*TBt)/128)               // 128 copy y-blocks
#define USLAB (Bn*2048)

// ---------------- fp32 scratch ----------------
constexpr size_t OFF_UGHP = 0;                               // 4 x (B x 2048)
constexpr size_t OFF_GIP  = OFF_UGHP + (size_t)4*Bn*2048;    // 5 x (B x 1536)
constexpr size_t OFF_GENP = OFF_GIP  + (size_t)5*Bn*G3H;     // 4 x (B x 3000)
constexpr size_t OFF_SP   = OFF_GENP + (size_t)4*Bn*Vd;      // MATT x 4 score partials
constexpr size_t OFF_HNEW = OFF_SP   + (size_t)MATT*4;
constexpr size_t OFF_CPR  = OFF_HNEW + (size_t)Bn*Hd;
constexpr size_t TOT_F32  = OFF_CPR  + (size_t)Bn*TBt;
__device__ float g_scratch[TOT_F32];

// ---------------- bf16 scratch ----------------
constexpr size_t BOFF_W1   = 0;                              // 512x512
constexpr size_t BOFF_WHH  = BOFF_W1  + (size_t)512*512;     // 1536x512
constexpr size_t BOFF_W2   = BOFF_WHH + (size_t)1536*512;
constexpr size_t BOFF_WC   = BOFF_W2  + (size_t)512*512;
constexpr size_t BOFF_WG   = BOFF_WC  + (size_t)512*512;     // 3000x512
constexpr size_t BOFF_WIH  = BOFF_WG  + (size_t)3000*512;    // 1536x2080
constexpr size_t BOFF_H0   = BOFF_WIH + (size_t)1536*2080;   // 128x512
constexpr size_t BOFF_X    = BOFF_H0  + (size_t)Bn*Hd;       // 128x2080 (bf16 GRU input)
constexpr size_t BOFF_HN   = BOFF_X   + (size_t)Bn*XD;       // 128x512
constexpr size_t BOFF_TBCP = BOFF_HN  + (size_t)Bn*Hd;       // 16384x512 tanh(copy)
constexpr size_t TOT_BF    = BOFF_TBCP+ (size_t)Bn*TBt*Hd;
__device__ __nv_bfloat16 g_bf[TOT_BF];

__device__ __forceinline__ float sigmoidf_(float x) { return 1.0f / (1.0f + expf(-x)); }

// ---------------- converts ----------------
__global__ void conv_weights_k(const float* __restrict__ aw, const float* __restrict__ wc,
                               const float* __restrict__ wg, const float* __restrict__ wih,
                               const float* __restrict__ whh, const float* __restrict__ h0,
                               __nv_bfloat16* __restrict__ bf) {
    int i = blockIdx.x * 256 + threadIdx.x;
    if (i < 262144)       { int r = i >> 9, c = i & 511; bf[BOFF_W1 + i] = __float2bfloat16(aw[(size_t)r * 1024 + c]); }
    else if (i < 524288)  { int j = i - 262144; int r = j >> 9, c = j & 511; bf[BOFF_W2 + j] = __float2bfloat16(aw[(size_t)r * 1024 + 512 + c]); }
    else if (i < 786432)  { int j = i - 524288;  bf[BOFF_WC  + j] = __float2bfloat16(wc[j]); }
    else if (i < 2322432) { int j = i - 786432;  bf[BOFF_WG  + j] = __float2bfloat16(wg[j]); }
    else if (i < 5517312) { int j = i - 2322432; bf[BOFF_WIH + j] = __float2bfloat16(wih[j]); }
    else if (i < 6303744) { int j = i - 5517312; bf[BOFF_WHH + j] = __float2bfloat16(whh[j]); }
    else if (i < 6369280) { int j = i - 6303744; bf[BOFF_H0  + j] = __float2bfloat16(h0[j]); }
}

// ---------------- mma helpers ----------------
__device__ __forceinline__ uint32_t sptr(const void* p) {
    return (uint32_t)__cvta_generic_to_shared(p);
}
__device__ __forceinline__ void ldsm_x4(uint32_t& r0, uint32_t& r1, uint32_t& r2, uint32_t& r3, uint32_t a) {
    asm volatile("ldmatrix.sync.aligned.m8n8.x4.shared.b16 {%0,%1,%2,%3}, [%4];\n"
                 : "=r"(r0), "=r"(r1), "=r"(r2), "=r"(r3) : "r"(a));
}
__device__ __forceinline__ void mma_bf16(float* d, const uint32_t* a, const uint32_t* b) {
    asm volatile("mma.sync.aligned.m16n8k16.row.col.f32.bf16.bf16.f32 "
                 "{%0,%1,%2,%3},{%4,%5,%6,%7},{%8,%9},{%0,%1,%2,%3};\n"
                 : "+f"(d[0]), "+f"(d[1]), "+f"(d[2]), "+f"(d[3])
                 : "r"(a[0]), "r"(a[1]), "r"(a[2]), "r"(a[3]), "r"(b[0]), "r"(b[1]));
}
__device__ __forceinline__ void cp16(uint32_t dst, const void* src, bool pred) {
    int sz = pred ? 16 : 0;
    asm volatile("cp.async.cg.shared.global [%0], [%1], 16, %2;\n"
                 :: "r"(dst), "l"(src), "r"(sz));
}
__device__ __forceinline__ void cp_commit() { asm volatile("cp.async.commit_group;\n"); }
template<int Nw> __device__ __forceinline__ void cp_wait() {
    asm volatile("cp.async.wait_group %0;\n" :: "n"(Nw));
}

#define GPAD 40
#define SKSTG 3
constexpr int DSMEM_SK = SKSTG * 2 * 128 * GPAD * 2;          // 61440

__device__ __forceinline__ int bat_of(int r) {
    return (r < Bn*TU) ? (r >> 8)
         : (r < Bn*TU + Bn*TBt) ? ((r - Bn*TU) >> 7)
         : ((r - Bn*TU - Bn*TBt) >> 6);
}

// ---------------- skinny split-K GEMM (M=128 tiles) ----------------
__global__ __launch_bounds__(256) void skinny_gemm_k(
    const __nv_bfloat16* __restrict__ A, int lda,
    const __nv_bfloat16* __restrict__ Bw, int ldb,
    float* __restrict__ Cp, int M, int N, int Kc)
{
    extern __shared__ __align__(16) __nv_bfloat16 dsm[];
    __nv_bfloat16* As = dsm;
    __nv_bfloat16* Bs = dsm + (size_t)SKSTG * 128 * GPAD;
    int tid = threadIdx.x;
    int warp = tid >> 5, lane = tid & 31;
    int m0 = blockIdx.y * 128, n0 = blockIdx.x * 128;
    int koff = blockIdx.z * Kc;
    float* C = Cp + (size_t)blockIdx.z * M * N;
    int wm = (warp >> 2) * 64, wn = (warp & 3) * 32;

    float acc[4][4][4];
    #pragma unroll
    for (int i = 0; i < 4; i++)
        #pragma unroll
        for (int j = 0; j < 4; j++)
            #pragma unroll
            for (int q = 0; q < 4; q++) acc[i][j][q] = 0.f;

    int lr = tid >> 1;
    int lc0 = (tid & 1) * 16;
    auto load_stage = [&](int st, int k0) {
        __nv_bfloat16* as = As + (size_t)st * 128 * GPAD;
        __nv_bfloat16* bs = Bs + (size_t)st * 128 * GPAD;
        #pragma unroll
        for (int s = 0; s < 2; s++) {
            int c = lc0 + s * 8;
            cp16(sptr(as + lr * GPAD + c), A + (size_t)(m0 + lr) * lda + koff + k0 + c, true);
            int gn = n0 + lr;
            bool pred = gn < N;
            cp16(sptr(bs + lr * GPAD + c),
                 Bw + (size_t)(pred ? gn : (N - 1)) * ldb + koff + k0 + c, pred);
        }
        cp_commit();
    };

    int nk = Kc >> 5;
    load_stage(0, 0);
    load_stage(1, 32);
    for (int it = 0; it < nk; it++) {
        if (it == nk - 1) cp_wait<0>(); else cp_wait<1>();
        __syncthreads();
        if (it + 2 < nk) load_stage((it + 2) % SKSTG, (it + 2) * 32);
        int cur = it % SKSTG;
        __nv_bfloat16* as = As + (size_t)cur * 128 * GPAD;
        __nv_bfloat16* bs = Bs + (size_t)cur * 128 * GPAD;
        #pragma unroll
        for (int kk = 0; kk < 2; kk++) {
            int kb = kk * 16;
            uint32_t afr[4][4], bfr[4][2];
            #pragma unroll
            for (int mt = 0; mt < 4; mt++) {
                int row = wm + mt * 16 + (lane & 15);
                int col = kb + (lane >> 4) * 8;
                ldsm_x4(afr[mt][0], afr[mt][1], afr[mt][2], afr[mt][3],
                        sptr(as + row * GPAD + col));
            }
            #pragma unroll
            for (int p = 0; p < 2; p++) {
                int row = wn + p * 16 + (lane & 7) + ((lane >> 4) & 1) * 8;
                int col = kb + ((lane >> 3) & 1) * 8;
                ldsm_x4(bfr[2*p][0], bfr[2*p][1], bfr[2*p+1][0], bfr[2*p+1][1],
                        sptr(bs + row * GPAD + col));
            }
            #pragma unroll
            for (int mt = 0; mt < 4; mt++)
                #pragma unroll
                for (int nt = 0; nt < 4; nt++)
                    mma_bf16(acc[mt][nt], afr[mt], bfr[nt]);
        }
    }
    #pragma unroll
    for (int mt = 0; mt < 4; mt++) {
        int r = m0 + wm + mt * 16 + (lane >> 2);
        #pragma unroll
        for (int nt = 0; nt < 4; nt++) {
            int col = n0 + wn + nt * 8 + (lane & 3) * 2;
            if (col < N) {
                *(float2*)(C + (size_t)r * N + col)       = make_float2(acc[mt][nt][0], acc[mt][nt][1]);
                *(float2*)(C + (size_t)(r + 8) * N + col) = make_float2(acc[mt][nt][2], acc[mt][nt][3]);
            }
        }
    }
}

// ---------------- fused big GEMM: 256 threads, 128x128 tile, 2 blocks/SM ----------------
// grid (4, YATT+YCPY). A read as fp32 (inline convert). K=512 in 16 chunks of 32.
__global__ __launch_bounds__(256, 2) void fused_gemm_k(
    const float* __restrict__ eu, const float* __restrict__ eb, const float* __restrict__ ep,
    const __nv_bfloat16* __restrict__ bf, const float* __restrict__ wcb,
    __nv_bfloat16* __restrict__ bTB, float* __restrict__ spart,
    const float* __restrict__ up, const float* __restrict__ ab,
    const float* __restrict__ v)
{
    constexpr int K = 512;
    constexpr int N = 512;
    extern __shared__ __align__(16) __nv_bfloat16 dsm[];
    __nv_bfloat16* Asm = dsm;                                  // [3][128*GPAD]
    __nv_bfloat16* Bsm = dsm + (size_t)3 * 128 * GPAD;         // [3][128*GPAD]
    __shared__ float part[128][4];
    int tid = threadIdx.x;
    int warp = tid >> 5, lane = tid & 31;
    int by = blockIdx.y;
    bool isAtt = by < YATT;
    const float* A; int mloc;
    if (!isAtt)        { A = eb; mloc = (by - YATT) * 128; }
    else if (by < 256) { A = eu; mloc = by * 128; }
    else if (by < 384) { A = eb; mloc = (by - 256) * 128; }
    else               { A = ep; mloc = (by - 384) * 128; }
    int m0g = by * 128;
    const __nv_bfloat16* Bw = isAtt ? (bf + BOFF_W2) : (bf + BOFF_WC);
    int n0 = blockIdx.x * 128;
    int wm = (warp >> 2) * 64, wn = (warp & 3) * 32;

    float acc[4][4][4];
    #pragma unroll
    for (int i = 0; i < 4; i++)
        #pragma unroll
        for (int j = 0; j < 4; j++)
            #pragma unroll
            for (int q = 0; q < 4; q++) acc[i][j][q] = 0.f;

    // A: fp32 -> bf16 smem. thread: row = tid>>1, cols (tid&1)*16 .. +16
    int arow = tid >> 1, acg = (tid & 1) * 16;
    const float* aptr = A + (size_t)(mloc + arow) * K + acg;
    // B loader (cp.async)
    int lr = tid >> 1, lc0 = (tid & 1) * 16;
    auto load_stage = [&](int st, int chunk) {
        int koff = chunk * 32;
        // A: 16 fp32 -> 16 bf16
        const float4* ap = (const float4*)(aptr + koff);
        float4 f0 = ap[0], f1 = ap[1], f2 = ap[2], f3 = ap[3];
        uint4 pk0, pk1;
        __nv_bfloat162 t0 = __floats2bfloat162_rn(f0.x, f0.y);
        __nv_bfloat162 t1 = __floats2bfloat162_rn(f0.z, f0.w);
        __nv_bfloat162 t2 = __floats2bfloat162_rn(f1.x, f1.y);
        __nv_bfloat162 t3 = __floats2bfloat162_rn(f1.z, f1.w);
        pk0.x = *(uint32_t*)&t0; pk0.y = *(uint32_t*)&t1;
        pk0.z = *(uint32_t*)&t2; pk0.w = *(uint32_t*)&t3;
        t0 = __floats2bfloat162_rn(f2.x, f2.y);
        t1 = __floats2bfloat162_rn(f2.z, f2.w);
        t2 = __floats2bfloat162_rn(f3.x, f3.y);
        t3 = __floats2bfloat162_rn(f3.z, f3.w);
        pk1.x = *(uint32_t*)&t0; pk1.y = *(uint32_t*)&t1;
        pk1.z = *(uint32_t*)&t2; pk1.w = *(uint32_t*)&t3;
        __nv_bfloat16* as = Asm + (size_t)st * 128 * GPAD + arow * GPAD + acg;
        *(uint4*)as       = pk0;
        *(uint4*)(as + 8) = pk1;
        // B via cp.async
        __nv_bfloat16* bs = Bsm + (size_t)st * 128 * GPAD;
        #pragma unroll
        for (int s = 0; s < 2; s++) {
            int c = lc0 + s * 8;
            cp16(sptr(bs + lr * GPAD + c), Bw + (size_t)(n0 + lr) * K + koff + c, true);
        }
        cp_commit();
    };

    constexpr int nk = K / 32;   // 16
    load_stage(0, 0);
    load_stage(1, 1);
    for (int c = 0; c < nk; c++) {
        if (c == nk - 1) cp_wait<0>(); else cp_wait<1>();
        __syncthreads();
        if (c + 2 < nk) load_stage((c + 2) % 3, c + 2);
        int cur = c % 3;
        __nv_bfloat16* as = Asm + (size_t)cur * 128 * GPAD;
        __nv_bfloat16* bs = Bsm + (size_t)cur * 128 * GPAD;
        #pragma unroll
        for (int kk = 0; kk < 2; kk++) {
            int kb = kk * 16;
            uint32_t afr[4][4], bfr[4][2];
            #pragma unroll
            for (int mt = 0; mt < 4; mt++) {
                int row = wm + mt * 16 + (lane & 15);
                int col = kb + (lane >> 4) * 8;
                ldsm_x4(afr[mt][0], afr[mt][1], afr[mt][2], afr[mt][3],
                        sptr(as + row * GPAD + col));
            }
            #pragma unroll
            for (int p = 0; p < 2; p++) {
                int row = wn + p * 16 + (lane & 7) + ((lane >> 4) & 1) * 8;
                int col = kb + ((lane >> 3) & 1) * 8;
                ldsm_x4(bfr[2*p][0], bfr[2*p][1], bfr[2*p+1][0], bfr[2*p+1][1],
                        sptr(bs + row * GPAD + col));
            }
            #pragma unroll
            for (int mt = 0; mt < 4; mt++)
                #pragma unroll
                for (int nt = 0; nt < 4; nt++)
                    mma_bf16(acc[mt][nt], afr[mt], bfr[nt]);
        }
    }

    if (!isAtt) {
        // tanh epilogue -> bf16 bTB
        #pragma unroll
        for (int mt = 0; mt < 4; mt++) {
            int r = mloc + wm + mt * 16 + (lane >> 2);
            #pragma unroll
            for (int nt = 0; nt < 4; nt++) {
                int col = n0 + wn + nt * 8 + (lane & 3) * 2;
                float b0 = wcb[col], b1 = wcb[col + 1];
                *(__nv_bfloat162*)(bTB + (size_t)r * N + col) =
                    __floats2bfloat162_rn(tanhf(acc[mt][nt][0] + b0), tanhf(acc[mt][nt][1] + b1));
                *(__nv_bfloat162*)(bTB + (size_t)(r + 8) * N + col) =
                    __floats2bfloat162_rn(tanhf(acc[mt][nt][2] + b0), tanhf(acc[mt][nt][3] + b1));
            }
        }
    } else {
        // score epilogue
        #pragma unroll
        for (int mt = 0; mt < 4; mt++) {
            int r0 = wm + mt * 16 + (lane >> 2);
            int r1 = r0 + 8;
            const float* u0 = up + (size_t)bat_of(m0g + r0) * 2048;
            const float* u1 = up + (size_t)bat_of(m0g + r1) * 2048;
            float ls0 = 0.f, ls1 = 0.f;
            #pragma unroll
            for (int nt = 0; nt < 4; nt++) {
                int col = n0 + wn + nt * 8 + (lane & 3) * 2;
                #pragma unroll
                for (int q = 0; q < 2; q++) {
                    int cI = col + q;
                    float uv0 = u0[cI] + u0[USLAB + cI] + u0[2*USLAB + cI] + u0[3*USLAB + cI] + ab[cI];
                    float uv1 = u1[cI] + u1[USLAB + cI] + u1[2*USLAB + cI] + u1[3*USLAB + cI] + ab[cI];
                    float vv = v[cI];
                    ls0 += vv * tanhf(acc[mt][nt][q]     + uv0);
                    ls1 += vv * tanhf(acc[mt][nt][2 + q] + uv1);
                }
            }
            #pragma unroll
            for (int s = 1; s < 4; s <<= 1) {
                ls0 += __shfl_xor_sync(0xffffffffu, ls0, s);
                ls1 += __shfl_xor_sync(0xffffffffu, ls1, s);
            }
            if ((lane & 3) == 0) {
                part[r0][warp & 3] = ls0;
                part[r1][warp & 3] = ls1;
            }
        }
        __syncthreads();
        if (tid < 128) {
            float tot = part[tid][0] + part[tid][1] + part[tid][2] + part[tid][3];
            spart[(size_t)(m0g + tid) * 4 + blockIdx.x] = tot;
        }
    }
}

// ---------------- merged softmax + ctx (fp32 enc, bf16 x out) ----------------
__global__ void softmax_ctx_all_k(const float* __restrict__ sp,
                                  const int* __restrict__ ids_u, const int* __restrict__ ids_b,
                                  const int* __restrict__ ids_p,
                                  const float* __restrict__ eu, const float* __restrict__ eb,
                                  const float* __restrict__ ep, __nv_bfloat16* __restrict__ bx) {
    int b = blockIdx.x, chunk = blockIdx.y, seg = blockIdx.z, tid = threadIdx.x;
    int T; const int* ids; const float* enc; int tokbase;
    if (seg == 0)      { T = TU;  ids = ids_u; enc = eu; tokbase = 0; }
    else if (seg == 1) { T = TBt; ids = ids_b; enc = eb; tokbase = Bn*TU; }
    else               { T = TPt; ids = ids_p; enc = ep; tokbase = Bn*TU + Bn*TBt; }
    __shared__ float sw[256];
    __shared__ float red[256];
    float sv = -3.0e38f;
    if (tid < T) {
        const float* s4 = sp + (size_t)(tokbase + b * T + tid) * 4;
        sv = (s4[0] + s4[1]) + (s4[2] + s4[3]);
        if (ids[(size_t)b * T + tid] == 0) sv = NEGV;
    }
    red[tid] = sv; __syncthreads();
    for (int s = 128; s; s >>= 1) { if (tid < s) red[tid] = fmaxf(red[tid], red[tid + s]); __syncthreads(); }
    float m = red[0]; __syncthreads();
    float e = (tid < T) ? expf(sv - m) : 0.f;
    red[tid] = e; __syncthreads();
    for (int s = 128; s; s >>= 1) { if (tid < s) red[tid] += red[tid + s]; __syncthreads(); }
    float Z = red[0]; __syncthreads();
    sw[tid] = e / Z; __syncthreads();
    int h = chunk * 256 + tid;
    float acc = 0.f;
    const float* epp = enc + (size_t)b * T * Hd + h;
    #pragma unroll 4
    for (int t = 0; t < T; t++) acc += sw[t] * epp[(size_t)t * Hd];
    bx[(size_t)b * XD + Ed + seg * Hd + h] = __float2bfloat16(acc);
}

// ---------------- x: emb + db slots (bf16) ----------------
__global__ void fill_x_k(const int* __restrict__ w, const float* __restrict__ emb_table,
                         const float* __restrict__ db, __nv_bfloat16* __restrict__ bx) {
    int b = blockIdx.x, tid = threadIdx.x;
    int wid = w[b];
    for (int i = tid; i < Ed; i += 256) bx[(size_t)b * XD + i] = __float2bfloat16(emb_table[(size_t)wid * Ed + i]);
    for (int i = tid; i < PTRd; i += 256) bx[(size_t)b * XD + Ed + 3 * Hd + i] = __float2bfloat16(db[(size_t)b * PTRd + i]);
}

// ---------------- GRU cell ----------------
__global__ void gru_cell_k(const float* __restrict__ gip, const float* __restrict__ ughp,
                           const float* __restrict__ bih, const float* __restrict__ bhh,
                           const float* __restrict__ h0, float* __restrict__ hnew,
                           __nv_bfloat16* __restrict__ hnbf) {
    int i = blockIdx.x * 256 + threadIdx.x;
    if (i >= Bn * Hd) return;
    int b = i / Hd, j = i % Hd;
    float gi[3], gh[3];
    #pragma unroll
    for (int g = 0; g < 3; g++) {
        int col = g * Hd + j;
        float s = bih[col];
        #pragma unroll
        for (int z = 0; z < 5; z++) s += gip[(size_t)z * Bn * G3H + (size_t)b * G3H + col];
        gi[g] = s;
        float t = bhh[col];
        #pragma unroll
        for (int z = 0; z < 4; z++) t += ughp[(size_t)z * USLAB + (size_t)b * 2048 + 512 + col];
        gh[g] = t;
    }
    float r = sigmoidf_(gi[0] + gh[0]);
    float z = sigmoidf_(gi[1] + gh[1]);
    float n = tanhf(gi[2] + r * gh[2]);
    float hv = (1.f - z) * n + z * h0[i];
    hnew[i] = hv;
    hnbf[i] = __float2bfloat16(hv);
}

// ---------------- cp_raw ----------------
__global__ void cpraw_k(const __nv_bfloat16* __restrict__ TB, const float* __restrict__ hnew,
                        const int* __restrict__ ids, float* __restrict__ cpr) {
    int tok = blockIdx.x * 8 + (threadIdx.x >> 5);
    int lane = threadIdx.x & 31;
    int b = tok / TBt;
    const __nv_bfloat162* e2 = (const __nv_bfloat162*)(TB + (size_t)tok * Hd);
    const float2* hn2 = (const float2*)(hnew + (size_t)b * Hd);
    float acc = 0.f;
    #pragma unroll 4
    for (int j = lane; j < Hd / 2; j += 32) {
        __nv_bfloat162 p = e2[j];
        float2 h2 = hn2[j];
        acc += h2.x * __bfloat162float(p.x) + h2.y * __bfloat162float(p.y);
    }
    #pragma unroll
    for (int s = 16; s; s >>= 1) acc += __shfl_down_sync(0xffffffffu, acc, s);
    if (lane == 0) cpr[tok] = (ids[tok] == 0) ? NEGV : acc;
}

// ---------------- final epilogue ----------------
__global__ void final_k(const float* __restrict__ genp, const float* __restrict__ genb,
                        const float* __restrict__ cpr, const int* __restrict__ nounk,
                        float* __restrict__ out) {
    int b = blockIdx.x, tid = threadIdx.x;
    __shared__ float Lg[Vd];
    __shared__ float Lc[Vd + TBt];
    __shared__ float addv[VOOVd - Vd];
    __shared__ float red[256];
    for (int n = tid; n < Vd; n += 256) {
        float s = genb[n];
        #pragma unroll
        for (int z = 0; z < 4; z++) s += genp[(size_t)z * Bn * Vd + (size_t)b * Vd + n];
        Lg[n] = s;
    }
    for (int n = tid; n < Vd + TBt; n += 256) Lc[n] = 0.f;
    for (int n = tid; n < VOOVd - Vd; n += 256) addv[n] = 0.f;
    __syncthreads();
    if (tid == 0) {
        for (int t = 0; t < TBt; t++) {
            int nk = nounk[(size_t)b * TBt + t];
            int col = (nk < Vd) ? nk : (Vd + t);
            Lc[col] += cpr[(size_t)b * TBt + t];
        }
    }
    __syncthreads();
    float lm = -3.0e38f;
    for (int n = tid; n < 2 * Vd + TBt; n += 256) {
        float v = (n < Vd) ? Lg[n] : Lc[n - Vd];
        lm = fmaxf(lm, v);
    }
    red[tid] = lm; __syncthreads();
    for (int s = 128; s; s >>= 1) { if (tid < s) red[tid] = fmaxf(red[tid], red[tid + s]); __syncthreads(); }
    float M = red[0]; __syncthreads();
    float ls = 0.f;
    for (int n = tid; n < 2 * Vd + TBt; n += 256) {
        float v = (n < Vd) ? Lg[n] : Lc[n - Vd];
        ls += expf(v - M);
    }
    red[tid] = ls; __syncthreads();
    for (int s = 128; s; s >>= 1) { if (tid < s) red[tid] += red[tid + s]; __syncthreads(); }
    float logZ = M + logf(red[0]); __syncthreads();
    if (tid == 0) {
        for (int t = 0; t < TBt; t++) {
            int nk = nounk[(size_t)b * TBt + t];
            if (nk >= Vd) addv[nk - Vd] += expf(Lc[Vd + t] - logZ);
        }
    }
    __syncthreads();
    for (int n = tid; n < VOOVd; n += 256) {
        float val;
        if (n < Vd) {
            float a = Lg[n] - logZ;
            float c = Lc[n] - logZ;
            float mm = fmaxf(a, c);
            val = mm + log1pf(expf(-fabsf(a - c)));
        } else {
            float v = addv[n - Vd];
            val = (v > 0.f) ? logf(fmaxf(v, 1e-38f)) : NEGV;
        }
        out[(size_t)b * VOOVd + n] = val;
    }
}

// ---------------- host ----------------
static inline int cdiv(int a, int b) { return (a + b - 1) / b; }

extern "C" void kernel_launch(void* const* d_in, const int* in_sizes, int n_in,
                              void* d_out, int out_size) {
    const int*   dec_last_w = (const int*)  d_in[0];
    const float* h0         = (const float*)d_in[1];
    const float* usdx_h     = (const float*)d_in[2];
    const float* bspn_h     = (const float*)d_in[3];
    const float* pv_h       = (const float*)d_in[4];
    const float* db         = (const float*)d_in[5];
    const int*   usdx_ids   = (const int*)  d_in[6];
    const int*   bspn_ids   = (const int*)  d_in[7];
    const int*   pv_ids     = (const int*)  d_in[8];
    const int*   nounk      = (const int*)  d_in[9];
    // d_in[10] = bspn_onehot: unused
    const float* emb        = (const float*)d_in[11];
    const float* attn_W     = (const float*)d_in[12];
    const float* attn_b     = (const float*)d_in[13];
    const float* v_w        = (const float*)d_in[14];
    const float* Wc         = (const float*)d_in[15];
    const float* Wcb        = (const float*)d_in[16];
    const float* Wg         = (const float*)d_in[17];
    const float* Wgb        = (const float*)d_in[18];
    const float* Wih        = (const float*)d_in[19];
    const float* Whh        = (const float*)d_in[20];
    const float* bih        = (const float*)d_in[21];
    const float* bhh        = (const float*)d_in[22];
    float* out = (float*)d_out;

    float* S = nullptr;  cudaGetSymbolAddress((void**)&S, g_scratch);
    __nv_bfloat16* Bf = nullptr;  cudaGetSymbolAddress((void**)&Bf, g_bf);

    float* UGHP = S + OFF_UGHP;
    float* GIP  = S + OFF_GIP;
    float* GENP = S + OFF_GENP;
    float* SP   = S + OFF_SP;
    float* HNEW = S + OFF_HNEW;
    float* CPR  = S + OFF_CPR;

    __nv_bfloat16* bW1c = Bf + BOFF_W1;
    __nv_bfloat16* bWG  = Bf + BOFF_WG;
    __nv_bfloat16* bWIH = Bf + BOFF_WIH;
    __nv_bfloat16* bH0  = Bf + BOFF_H0;
    __nv_bfloat16* bX   = Bf + BOFF_X;
    __nv_bfloat16* bHN  = Bf + BOFF_HN;
    __nv_bfloat16* bTB  = Bf + BOFF_TBCP;

    static bool attr_set = false;
    if (!attr_set) {
        cudaFuncSetAttribute(skinny_gemm_k, cudaFuncAttributeMaxDynamicSharedMemorySize, DSMEM_SK);
        cudaFuncSetAttribute(fused_gemm_k, cudaFuncAttributeMaxDynamicSharedMemorySize, DSMEM_SK);
        attr_set = true;
    }

    // 0: weight converts
    conv_weights_k<<<cdiv(6369280, 256), 256>>>(attn_W, Wc, Wg, Wih, Whh, h0, Bf);
    // 1: UGH partials, splitK=4
    skinny_gemm_k<<<dim3(16, 1, 4), 256, DSMEM_SK>>>(bH0, 512, bW1c, 512, UGHP, Bn, 2048, 128);
    // 2: emb + db
    fill_x_k<<<Bn, 256>>>(dec_last_w, emb, db, bX);
    // 3 (profiled slot): fused GEMM, 2 blocks/SM
    fused_gemm_k<<<dim3(4, YATT + YCPY), 256, DSMEM_SK>>>(usdx_h, bspn_h, pv_h, Bf, Wcb, bTB, SP, UGHP, attn_b, v_w);
    // 4: softmax + ctx (fp32 enc, bf16 out)
    softmax_ctx_all_k<<<dim3(Bn, 2, 3), 256>>>(SP, usdx_ids, bspn_ids, pv_ids, usdx_h, bspn_h, pv_h, bX);
    // 5: GI partials, splitK=5, Kc=416
    skinny_gemm_k<<<dim3(12, 1, 5), 256, DSMEM_SK>>>(bX, XD, bWIH, XD, GIP, Bn, G3H, 416);
    // 6: GRU cell
    gru_cell_k<<<cdiv(Bn*Hd, 256), 256>>>(GIP, UGHP, bih, bhh, h0, HNEW, bHN);
    // 7: GEN partials, splitK=4
    skinny_gemm_k<<<dim3(cdiv(3000, 128), 1, 4), 256, DSMEM_SK>>>(bHN, 512, bWG, 512, GENP, Bn, Vd, 128);
    // 8: copy scores
    cpraw_k<<<(Bn*TBt)/8, 256>>>(bTB, HNEW, bspn_ids, CPR);
    // 9: final epilogue
    final_k<<<Bn, 256>>>(GENP, Wgb, CPR, nounk, out);
}

// round 13
// speedup vs baseline: 1.1441x; 1.1441x over previous
#include <cuda_runtime.h>
#include <cuda_bf16.h>
#include <math.h>
#include <stdint.h>

// ---------------- problem constants ----------------
#define Bn    128
#define TU    256
#define TBt   128
#define TPt   64
#define Hd    512
#define Ed    512
#define Vd    3000
#define VOOVd 3400
#define PTRd  32
#define XD    2080
#define G3H   1536
#define NEGV  (-1e20f)
#define MATT  (Bn*TU + Bn*TBt + Bn*TPt)   // 57344 merged attention rows
#define YATT  (MATT/128)                   // 448 attention y-blocks
#define YCPY  ((Bn*TBt)/128)               // 128 copy y-blocks
#define USLAB (Bn*2048)

// ---------------- fp32 scratch ----------------
constexpr size_t OFF_UGHP = 0;                               // 4 x (B x 2048)
constexpr size_t OFF_GIP  = OFF_UGHP + (size_t)4*Bn*2048;    // 5 x (B x 1536)
constexpr size_t OFF_GENP = OFF_GIP  + (size_t)5*Bn*G3H;     // 4 x (B x 3000)
constexpr size_t OFF_SP   = OFF_GENP + (size_t)4*Bn*Vd;      // MATT x 2 score partials
constexpr size_t OFF_HNEW = OFF_SP   + (size_t)MATT*2;
constexpr size_t OFF_CPR  = OFF_HNEW + (size_t)Bn*Hd;
constexpr size_t TOT_F32  = OFF_CPR  + (size_t)Bn*TBt;
__device__ float g_scratch[TOT_F32];

// ---------------- bf16 scratch ----------------
constexpr size_t BOFF_W1   = 0;                              // 512x512
constexpr size_t BOFF_WHH  = BOFF_W1  + (size_t)512*512;     // 1536x512
constexpr size_t BOFF_W2   = BOFF_WHH + (size_t)1536*512;
constexpr size_t BOFF_WC   = BOFF_W2  + (size_t)512*512;
constexpr size_t BOFF_WG   = BOFF_WC  + (size_t)512*512;     // 3000x512
constexpr size_t BOFF_WIH  = BOFF_WG  + (size_t)3000*512;    // 1536x2080
constexpr size_t BOFF_H0   = BOFF_WIH + (size_t)1536*2080;   // 128x512
constexpr size_t BOFF_X    = BOFF_H0  + (size_t)Bn*Hd;       // 128x2080 (bf16 GRU input)
constexpr size_t BOFF_HN   = BOFF_X   + (size_t)Bn*XD;       // 128x512
constexpr size_t BOFF_TBCP = BOFF_HN  + (size_t)Bn*Hd;       // 16384x512 tanh(copy)
constexpr size_t TOT_BF    = BOFF_TBCP+ (size_t)Bn*TBt*Hd;
__device__ __nv_bfloat16 g_bf[TOT_BF];

// ---------------- fast transcendentals ----------------
__device__ __forceinline__ float tanh_fast(float x) {
    float y;
    asm("tanh.approx.f32 %0, %1;" : "=f"(y) : "f"(x));
    return y;
}
__device__ __forceinline__ float exp_fast(float x) {
    float y;
    asm("ex2.approx.f32 %0, %1;" : "=f"(y) : "f"(x * 1.4426950408889634f));
    return y;
}
__device__ __forceinline__ float sigmoid_fast(float x) { return 1.0f / (1.0f + exp_fast(-x)); }

// ---------------- converts ----------------
__global__ void conv_weights_k(const float* __restrict__ aw, const float* __restrict__ wc,
                               const float* __restrict__ wg, const float* __restrict__ wih,
                               const float* __restrict__ whh, const float* __restrict__ h0,
                               __nv_bfloat16* __restrict__ bf) {
    int i = blockIdx.x * 256 + threadIdx.x;
    if (i < 262144)       { int r = i >> 9, c = i & 511; bf[BOFF_W1 + i] = __float2bfloat16(aw[(size_t)r * 1024 + c]); }
    else if (i < 524288)  { int j = i - 262144; int r = j >> 9, c = j & 511; bf[BOFF_W2 + j] = __float2bfloat16(aw[(size_t)r * 1024 + 512 + c]); }
    else if (i < 786432)  { int j = i - 524288;  bf[BOFF_WC  + j] = __float2bfloat16(wc[j]); }
    else if (i < 2322432) { int j = i - 786432;  bf[BOFF_WG  + j] = __float2bfloat16(wg[j]); }
    else if (i < 5517312) { int j = i - 2322432; bf[BOFF_WIH + j] = __float2bfloat16(wih[j]); }
    else if (i < 6303744) { int j = i - 5517312; bf[BOFF_WHH + j] = __float2bfloat16(whh[j]); }
    else if (i < 6369280) { int j = i - 6303744; bf[BOFF_H0  + j] = __float2bfloat16(h0[j]); }
}

// ---------------- mma helpers ----------------
__device__ __forceinline__ uint32_t sptr(const void* p) {
    return (uint32_t)__cvta_generic_to_shared(p);
}
__device__ __forceinline__ void ldsm_x4(uint32_t& r0, uint32_t& r1, uint32_t& r2, uint32_t& r3, uint32_t a) {
    asm volatile("ldmatrix.sync.aligned.m8n8.x4.shared.b16 {%0,%1,%2,%3}, [%4];\n"
                 : "=r"(r0), "=r"(r1), "=r"(r2), "=r"(r3) : "r"(a));
}
__device__ __forceinline__ void mma_bf16(float* d, const uint32_t* a, const uint32_t* b) {
    asm volatile("mma.sync.aligned.m16n8k16.row.col.f32.bf16.bf16.f32 "
                 "{%0,%1,%2,%3},{%4,%5,%6,%7},{%8,%9},{%0,%1,%2,%3};\n"
                 : "+f"(d[0]), "+f"(d[1]), "+f"(d[2]), "+f"(d[3])
                 : "r"(a[0]), "r"(a[1]), "r"(a[2]), "r"(a[3]), "r"(b[0]), "r"(b[1]));
}
__device__ __forceinline__ void cp16(uint32_t dst, const void* src, bool pred) {
    int sz = pred ? 16 : 0;
    asm volatile("cp.async.cg.shared.global [%0], [%1], 16, %2;\n"
                 :: "r"(dst), "l"(src), "r"(sz));
}
__device__ __forceinline__ void cp_commit() { asm volatile("cp.async.commit_group;\n"); }
template<int Nw> __device__ __forceinline__ void cp_wait() {
    asm volatile("cp.async.wait_group %0;\n" :: "n"(Nw));
}

#define GPAD 40
#define SKSTG 3
constexpr int DSMEM_SK  = SKSTG * 2 * 128 * GPAD * 2;          // 61440
constexpr int DSMEM_BIG = 3 * (128 + 256) * GPAD * 2;          // 92160

__device__ __forceinline__ int bat_of(int r) {
    return (r < Bn*TU) ? (r >> 8)
         : (r < Bn*TU + Bn*TBt) ? ((r - Bn*TU) >> 7)
         : ((r - Bn*TU - Bn*TBt) >> 6);
}

// ---------------- skinny split-K GEMM (M=128 tiles) ----------------
__global__ __launch_bounds__(256) void skinny_gemm_k(
    const __nv_bfloat16* __restrict__ A, int lda,
    const __nv_bfloat16* __restrict__ Bw, int ldb,
    float* __restrict__ Cp, int M, int N, int Kc)
{
    extern __shared__ __align__(16) __nv_bfloat16 dsm[];
    __nv_bfloat16* As = dsm;
    __nv_bfloat16* Bs = dsm + (size_t)SKSTG * 128 * GPAD;
    int tid = threadIdx.x;
    int warp = tid >> 5, lane = tid & 31;
    int m0 = blockIdx.y * 128, n0 = blockIdx.x * 128;
    int koff = blockIdx.z * Kc;
    float* C = Cp + (size_t)blockIdx.z * M * N;
    int wm = (warp >> 2) * 64, wn = (warp & 3) * 32;

    float acc[4][4][4];
    #pragma unroll
    for (int i = 0; i < 4; i++)
        #pragma unroll
        for (int j = 0; j < 4; j++)
            #pragma unroll
            for (int q = 0; q < 4; q++) acc[i][j][q] = 0.f;

    int lr = tid >> 1;
    int lc0 = (tid & 1) * 16;
    auto load_stage = [&](int st, int k0) {
        __nv_bfloat16* as = As + (size_t)st * 128 * GPAD;
        __nv_bfloat16* bs = Bs + (size_t)st * 128 * GPAD;
        #pragma unroll
        for (int s = 0; s < 2; s++) {
            int c = lc0 + s * 8;
            cp16(sptr(as + lr * GPAD + c), A + (size_t)(m0 + lr) * lda + koff + k0 + c, true);
            int gn = n0 + lr;
            bool pred = gn < N;
            cp16(sptr(bs + lr * GPAD + c),
                 Bw + (size_t)(pred ? gn : (N - 1)) * ldb + koff + k0 + c, pred);
        }
        cp_commit();
    };

    int nk = Kc >> 5;
    load_stage(0, 0);
    load_stage(1, 32);
    for (int it = 0; it < nk; it++) {
        if (it == nk - 1) cp_wait<0>(); else cp_wait<1>();
        __syncthreads();
        if (it + 2 < nk) load_stage((it + 2) % SKSTG, (it + 2) * 32);
        int cur = it % SKSTG;
        __nv_bfloat16* as = As + (size_t)cur * 128 * GPAD;
        __nv_bfloat16* bs = Bs + (size_t)cur * 128 * GPAD;
        #pragma unroll
        for (int kk = 0; kk < 2; kk++) {
            int kb = kk * 16;
            uint32_t afr[4][4], bfr[4][2];
            #pragma unroll
            for (int mt = 0; mt < 4; mt++) {
                int row = wm + mt * 16 + (lane & 15);
                int col = kb + (lane >> 4) * 8;
                ldsm_x4(afr[mt][0], afr[mt][1], afr[mt][2], afr[mt][3],
                        sptr(as + row * GPAD + col));
            }
            #pragma unroll
            for (int p = 0; p < 2; p++) {
                int row = wn + p * 16 + (lane & 7) + ((lane >> 4) & 1) * 8;
                int col = kb + ((lane >> 3) & 1) * 8;
                ldsm_x4(bfr[2*p][0], bfr[2*p][1], bfr[2*p+1][0], bfr[2*p+1][1],
                        sptr(bs + row * GPAD + col));
            }
            #pragma unroll
            for (int mt = 0; mt < 4; mt++)
                #pragma unroll
                for (int nt = 0; nt < 4; nt++)
                    mma_bf16(acc[mt][nt], afr[mt], bfr[nt]);
        }
    }
    #pragma unroll
    for (int mt = 0; mt < 4; mt++) {
        int r = m0 + wm + mt * 16 + (lane >> 2);
        #pragma unroll
        for (int nt = 0; nt < 4; nt++) {
            int col = n0 + wn + nt * 8 + (lane & 3) * 2;
            if (col < N) {
                *(float2*)(C + (size_t)r * N + col)       = make_float2(acc[mt][nt][0], acc[mt][nt][1]);
                *(float2*)(C + (size_t)(r + 8) * N + col) = make_float2(acc[mt][nt][2], acc[mt][nt][3]);
            }
        }
    }
}

// ---------------- fused big GEMM (R10 config): 512 threads, 128x256 tile, 3 stages ----------------
__global__ __launch_bounds__(512) void fused_gemm_k(
    const float* __restrict__ eu, const float* __restrict__ eb, const float* __restrict__ ep,
    const __nv_bfloat16* __restrict__ bf, const float* __restrict__ wcb,
    __nv_bfloat16* __restrict__ bTB, float* __restrict__ spart,
    const float* __restrict__ up, const float* __restrict__ ab,
    const float* __restrict__ v)
{
    constexpr int K = 512;
    constexpr int N = 512;
    extern __shared__ __align__(16) __nv_bfloat16 dsm[];
    __nv_bfloat16* Asm = dsm;                                  // [3][128*GPAD]
    __nv_bfloat16* Bsm = dsm + (size_t)3 * 128 * GPAD;         // [3][256*GPAD]
    __shared__ float part[128][4];
    int tid = threadIdx.x;
    int warp = tid >> 5, lane = tid & 31;
    int by = blockIdx.y;
    bool isAtt = by < YATT;
    const float* A; int mloc;
    if (!isAtt)        { A = eb; mloc = (by - YATT) * 128; }
    else if (by < 256) { A = eu; mloc = by * 128; }
    else if (by < 384) { A = eb; mloc = (by - 256) * 128; }
    else               { A = ep; mloc = (by - 384) * 128; }
    int m0g = by * 128;
    const __nv_bfloat16* Bw = isAtt ? (bf + BOFF_W2) : (bf + BOFF_WC);
    int n0 = blockIdx.x * 256;
    int wm = (warp >> 2) * 32, wn = (warp & 3) * 64;

    float acc[2][8][4];
    #pragma unroll
    for (int i = 0; i < 2; i++)
        #pragma unroll
        for (int j = 0; j < 8; j++)
            #pragma unroll
            for (int q = 0; q < 4; q++) acc[i][j][q] = 0.f;

    int arow = tid >> 2, acg = (tid & 3) * 8;
    const float* aptr = A + (size_t)(mloc + arow) * K + acg;
    float4 ar0, ar1;
    auto ldgA = [&](int chunk) {
        const float4* p = (const float4*)(aptr + chunk * 32);
        ar0 = p[0]; ar1 = p[1];
    };
    auto stsA = [&](int st) {
        uint4 pk;
        __nv_bfloat162 t0 = __floats2bfloat162_rn(ar0.x, ar0.y);
        __nv_bfloat162 t1 = __floats2bfloat162_rn(ar0.z, ar0.w);
        __nv_bfloat162 t2 = __floats2bfloat162_rn(ar1.x, ar1.y);
        __nv_bfloat162 t3 = __floats2bfloat162_rn(ar1.z, ar1.w);
        pk.x = *(uint32_t*)&t0; pk.y = *(uint32_t*)&t1;
        pk.z = *(uint32_t*)&t2; pk.w = *(uint32_t*)&t3;
        *(uint4*)(Asm + (size_t)st * 128 * GPAD + arow * GPAD + acg) = pk;
    };
    auto loadB = [&](int st, int chunk) {
        int koff = chunk * 32;
        __nv_bfloat16* bs = Bsm + (size_t)st * 256 * GPAD;
        #pragma unroll
        for (int s = 0; s < 2; s++) {
            int j = tid + s * 512;
            int br = j >> 2, bc = (j & 3) * 8;
            cp16(sptr(bs + br * GPAD + bc), Bw + (size_t)(n0 + br) * K + koff + bc, true);
        }
        cp_commit();
    };

    // prologue
    ldgA(0); stsA(0);
    ldgA(1); stsA(1);
    loadB(0, 0); loadB(1, 1);
    ldgA(2);

    constexpr int nk = K / 32;   // 16
    for (int c = 0; c < nk; c++) {
        if (c == nk - 1) cp_wait<0>(); else cp_wait<1>();
        __syncthreads();
        if (c + 2 < nk) {
            int st = (c + 2) % 3;
            stsA(st);
            loadB(st, c + 2);
            if (c + 3 < nk) ldgA(c + 3);
        }
        int cur = c % 3;
        __nv_bfloat16* as = Asm + (size_t)cur * 128 * GPAD;
        __nv_bfloat16* bs = Bsm + (size_t)cur * 256 * GPAD;
        #pragma unroll
        for (int kk = 0; kk < 2; kk++) {
            int kb = kk * 16;
            uint32_t afr[2][4], bfr[8][2];
            #pragma unroll
            for (int mt = 0; mt < 2; mt++) {
                int row = wm + mt * 16 + (lane & 15);
                int col = kb + (lane >> 4) * 8;
                ldsm_x4(afr[mt][0], afr[mt][1], afr[mt][2], afr[mt][3],
                        sptr(as + row * GPAD + col));
            }
            #pragma unroll
            for (int p = 0; p < 4; p++) {
                int row = wn + p * 16 + (lane & 7) + ((lane >> 4) & 1) * 8;
                int col = kb + ((lane >> 3) & 1) * 8;
                ldsm_x4(bfr[2*p][0], bfr[2*p][1], bfr[2*p+1][0], bfr[2*p+1][1],
                        sptr(bs + row * GPAD + col));
            }
            #pragma unroll
            for (int mt = 0; mt < 2; mt++)
                #pragma unroll
                for (int nt = 0; nt < 8; nt++)
                    mma_bf16(acc[mt][nt], afr[mt], bfr[nt]);
        }
    }

    if (!isAtt) {
        // tanh epilogue -> bf16 bTB
        #pragma unroll
        for (int mt = 0; mt < 2; mt++) {
            int r = mloc + wm + mt * 16 + (lane >> 2);
            #pragma unroll
            for (int nt = 0; nt < 8; nt++) {
                int col = n0 + wn + nt * 8 + (lane & 3) * 2;
                float b0 = wcb[col], b1 = wcb[col + 1];
                *(__nv_bfloat162*)(bTB + (size_t)r * N + col) =
                    __floats2bfloat162_rn(tanh_fast(acc[mt][nt][0] + b0), tanh_fast(acc[mt][nt][1] + b1));
                *(__nv_bfloat162*)(bTB + (size_t)(r + 8) * N + col) =
                    __floats2bfloat162_rn(tanh_fast(acc[mt][nt][2] + b0), tanh_fast(acc[mt][nt][3] + b1));
            }
        }
    } else {
        // score epilogue
        #pragma unroll
        for (int mt = 0; mt < 2; mt++) {
            int r0 = wm + mt * 16 + (lane >> 2);
            int r1 = r0 + 8;
            const float* u0 = up + (size_t)bat_of(m0g + r0) * 2048;
            const float* u1 = up + (size_t)bat_of(m0g + r1) * 2048;
            float ls0 = 0.f, ls1 = 0.f;
            #pragma unroll
            for (int nt = 0; nt < 8; nt++) {
                int col = n0 + wn + nt * 8 + (lane & 3) * 2;
                #pragma unroll
                for (int q = 0; q < 2; q++) {
                    int cI = col + q;
                    float uv0 = u0[cI] + u0[USLAB + cI] + u0[2*USLAB + cI] + u0[3*USLAB + cI] + ab[cI];
                    float uv1 = u1[cI] + u1[USLAB + cI] + u1[2*USLAB + cI] + u1[3*USLAB + cI] + ab[cI];
                    float vv = v[cI];
                    ls0 += vv * tanh_fast(acc[mt][nt][q]     + uv0);
                    ls1 += vv * tanh_fast(acc[mt][nt][2 + q] + uv1);
                }
            }
            #pragma unroll
            for (int s = 1; s < 4; s <<= 1) {
                ls0 += __shfl_xor_sync(0xffffffffu, ls0, s);
                ls1 += __shfl_xor_sync(0xffffffffu, ls1, s);
            }
            if ((lane & 3) == 0) {
                part[r0][warp & 3] = ls0;
                part[r1][warp & 3] = ls1;
            }
        }
        __syncthreads();
        if (tid < 128) {
            float tot = part[tid][0] + part[tid][1] + part[tid][2] + part[tid][3];
            spart[(size_t)(m0g + tid) * 2 + blockIdx.x] = tot;
        }
    }
}

// ---------------- merged softmax + ctx (fp32 enc, bf16 x out) ----------------
__global__ void softmax_ctx_all_k(const float* __restrict__ sp,
                                  const int* __restrict__ ids_u, const int* __restrict__ ids_b,
                                  const int* __restrict__ ids_p,
                                  const float* __restrict__ eu, const float* __restrict__ eb,
                                  const float* __restrict__ ep, __nv_bfloat16* __restrict__ bx) {
    int b = blockIdx.x, chunk = blockIdx.y, seg = blockIdx.z, tid = threadIdx.x;
    int T; const int* ids; const float* enc; int tokbase;
    if (seg == 0)      { T = TU;  ids = ids_u; enc = eu; tokbase = 0; }
    else if (seg == 1) { T = TBt; ids = ids_b; enc = eb; tokbase = Bn*TU; }
    else               { T = TPt; ids = ids_p; enc = ep; tokbase = Bn*TU + Bn*TBt; }
    __shared__ float sw[256];
    __shared__ float red[256];
    float sv = -3.0e38f;
    if (tid < T) {
        const float* s2 = sp + (size_t)(tokbase + b * T + tid) * 2;
        sv = s2[0] + s2[1];
        if (ids[(size_t)b * T + tid] == 0) sv = NEGV;
    }
    red[tid] = sv; __syncthreads();
    for (int s = 128; s; s >>= 1) { if (tid < s) red[tid] = fmaxf(red[tid], red[tid + s]); __syncthreads(); }
    float m = red[0]; __syncthreads();
    float e = (tid < T) ? exp_fast(sv - m) : 0.f;
    red[tid] = e; __syncthreads();
    for (int s = 128; s; s >>= 1) { if (tid < s) red[tid] += red[tid + s]; __syncthreads(); }
    float Z = red[0]; __syncthreads();
    sw[tid] = e / Z; __syncthreads();
    int h = chunk * 256 + tid;
    float acc = 0.f;
    const float* epp = enc + (size_t)b * T * Hd + h;
    #pragma unroll 4
    for (int t = 0; t < T; t++) acc += sw[t] * epp[(size_t)t * Hd];
    bx[(size_t)b * XD + Ed + seg * Hd + h] = __float2bfloat16(acc);
}

// ---------------- x: emb + db slots (bf16) ----------------
__global__ void fill_x_k(const int* __restrict__ w, const float* __restrict__ emb_table,
                         const float* __restrict__ db, __nv_bfloat16* __restrict__ bx) {
    int b = blockIdx.x, tid = threadIdx.x;
    int wid = w[b];
    for (int i = tid; i < Ed; i += 256) bx[(size_t)b * XD + i] = __float2bfloat16(emb_table[(size_t)wid * Ed + i]);
    for (int i = tid; i < PTRd; i += 256) bx[(size_t)b * XD + Ed + 3 * Hd + i] = __float2bfloat16(db[(size_t)b * PTRd + i]);
}

// ---------------- GRU cell ----------------
__global__ void gru_cell_k(const float* __restrict__ gip, const float* __restrict__ ughp,
                           const float* __restrict__ bih, const float* __restrict__ bhh,
                           const float* __restrict__ h0, float* __restrict__ hnew,
                           __nv_bfloat16* __restrict__ hnbf) {
    int i = blockIdx.x * 256 + threadIdx.x;
    if (i >= Bn * Hd) return;
    int b = i / Hd, j = i % Hd;
    float gi[3], gh[3];
    #pragma unroll
    for (int g = 0; g < 3; g++) {
        int col = g * Hd + j;
        float s = bih[col];
        #pragma unroll
        for (int z = 0; z < 5; z++) s += gip[(size_t)z * Bn * G3H + (size_t)b * G3H + col];
        gi[g] = s;
        float t = bhh[col];
        #pragma unroll
        for (int z = 0; z < 4; z++) t += ughp[(size_t)z * USLAB + (size_t)b * 2048 + 512 + col];
        gh[g] = t;
    }
    float r = sigmoid_fast(gi[0] + gh[0]);
    float z = sigmoid_fast(gi[1] + gh[1]);
    float n = tanh_fast(gi[2] + r * gh[2]);
    float hv = (1.f - z) * n + z * h0[i];
    hnew[i] = hv;
    hnbf[i] = __float2bfloat16(hv);
}

// ---------------- cp_raw ----------------
__global__ void cpraw_k(const __nv_bfloat16* __restrict__ TB, const float* __restrict__ hnew,
                        const int* __restrict__ ids, float* __restrict__ cpr) {
    int tok = blockIdx.x * 8 + (threadIdx.x >> 5);
    int lane = threadIdx.x & 31;
    int b = tok / TBt;
    const __nv_bfloat162* e2 = (const __nv_bfloat162*)(TB + (size_t)tok * Hd);
    const float2* hn2 = (const float2*)(hnew + (size_t)b * Hd);
    float acc = 0.f;
    #pragma unroll 4
    for (int j = lane; j < Hd / 2; j += 32) {
        __nv_bfloat162 p = e2[j];
        float2 h2 = hn2[j];
        acc += h2.x * __bfloat162float(p.x) + h2.y * __bfloat162float(p.y);
    }
    #pragma unroll
    for (int s = 16; s; s >>= 1) acc += __shfl_down_sync(0xffffffffu, acc, s);
    if (lane == 0) cpr[tok] = (ids[tok] == 0) ? NEGV : acc;
}

// ---------------- final epilogue ----------------
__global__ void final_k(const float* __restrict__ genp, const float* __restrict__ genb,
                        const float* __restrict__ cpr, const int* __restrict__ nounk,
                        float* __restrict__ out) {
    int b = blockIdx.x, tid = threadIdx.x;
    __shared__ float Lg[Vd];
    __shared__ float Lc[Vd + TBt];
    __shared__ float addv[VOOVd - Vd];
    __shared__ float red[256];
    for (int n = tid; n < Vd; n += 256) {
        float s = genb[n];
        #pragma unroll
        for (int z = 0; z < 4; z++) s += genp[(size_t)z * Bn * Vd + (size_t)b * Vd + n];
        Lg[n] = s;
    }
    for (int n = tid; n < Vd + TBt; n += 256) Lc[n] = 0.f;
    for (int n = tid; n < VOOVd - Vd; n += 256) addv[n] = 0.f;
    __syncthreads();
    if (tid == 0) {
        for (int t = 0; t < TBt; t++) {
            int nk = nounk[(size_t)b * TBt + t];
            int col = (nk < Vd) ? nk : (Vd + t);
            Lc[col] += cpr[(size_t)b * TBt + t];
        }
    }
    __syncthreads();
    float lm = -3.0e38f;
    for (int n = tid; n < 2 * Vd + TBt; n += 256) {
        float v = (n < Vd) ? Lg[n] : Lc[n - Vd];
        lm = fmaxf(lm, v);
    }
    red[tid] = lm; __syncthreads();
    for (int s = 128; s; s >>= 1) { if (tid < s) red[tid] = fmaxf(red[tid], red[tid + s]); __syncthreads(); }
    float M = red[0]; __syncthreads();
    float ls = 0.f;
    for (int n = tid; n < 2 * Vd + TBt; n += 256) {
        float v = (n < Vd) ? Lg[n] : Lc[n - Vd];
        ls += exp_fast(v - M);
    }
    red[tid] = ls; __syncthreads();
    for (int s = 128; s; s >>= 1) { if (tid < s) red[tid] += red[tid + s]; __syncthreads(); }
    float logZ = M + logf(red[0]); __syncthreads();
    if (tid == 0) {
        for (int t = 0; t < TBt; t++) {
            int nk = nounk[(size_t)b * TBt + t];
            if (nk >= Vd) addv[nk - Vd] += exp_fast(Lc[Vd + t] - logZ);
        }
    }
    __syncthreads();
    for (int n = tid; n < VOOVd; n += 256) {
        float val;
        if (n < Vd) {
            float a = Lg[n] - logZ;
            float c = Lc[n] - logZ;
            float mm = fmaxf(a, c);
            val = mm + log1pf(exp_fast(-fabsf(a - c)));
        } else {
            float v = addv[n - Vd];
            val = (v > 0.f) ? logf(fmaxf(v, 1e-38f)) : NEGV;
        }
        out[(size_t)b * VOOVd + n] = val;
    }
}

// ---------------- host ----------------
static inline int cdiv(int a, int b) { return (a + b - 1) / b; }

extern "C" void kernel_launch(void* const* d_in, const int* in_sizes, int n_in,
                              void* d_out, int out_size) {
    const int*   dec_last_w = (const int*)  d_in[0];
    const float* h0         = (const float*)d_in[1];
    const float* usdx_h     = (const float*)d_in[2];
    const float* bspn_h     = (const float*)d_in[3];
    const float* pv_h       = (const float*)d_in[4];
    const float* db         = (const float*)d_in[5];
    const int*   usdx_ids   = (const int*)  d_in[6];
    const int*   bspn_ids   = (const int*)  d_in[7];
    const int*   pv_ids     = (const int*)  d_in[8];
    const int*   nounk      = (const int*)  d_in[9];
    // d_in[10] = bspn_onehot: unused
    const float* emb        = (const float*)d_in[11];
    const float* attn_W     = (const float*)d_in[12];
    const float* attn_b     = (const float*)d_in[13];
    const float* v_w        = (const float*)d_in[14];
    const float* Wc         = (const float*)d_in[15];
    const float* Wcb        = (const float*)d_in[16];
    const float* Wg         = (const float*)d_in[17];
    const float* Wgb        = (const float*)d_in[18];
    const float* Wih        = (const float*)d_in[19];
    const float* Whh        = (const float*)d_in[20];
    const float* bih        = (const float*)d_in[21];
    const float* bhh        = (const float*)d_in[22];
    float* out = (float*)d_out;

    float* S = nullptr;  cudaGetSymbolAddress((void**)&S, g_scratch);
    __nv_bfloat16* Bf = nullptr;  cudaGetSymbolAddress((void**)&Bf, g_bf);

    float* UGHP = S + OFF_UGHP;
    float* GIP  = S + OFF_GIP;
    float* GENP = S + OFF_GENP;
    float* SP   = S + OFF_SP;
    float* HNEW = S + OFF_HNEW;
    float* CPR  = S + OFF_CPR;

    __nv_bfloat16* bW1c = Bf + BOFF_W1;
    __nv_bfloat16* bWG  = Bf + BOFF_WG;
    __nv_bfloat16* bWIH = Bf + BOFF_WIH;
    __nv_bfloat16* bH0  = Bf + BOFF_H0;
    __nv_bfloat16* bX   = Bf + BOFF_X;
    __nv_bfloat16* bHN  = Bf + BOFF_HN;
    __nv_bfloat16* bTB  = Bf + BOFF_TBCP;

    static bool attr_set = false;
    if (!attr_set) {
        cudaFuncSetAttribute(skinny_gemm_k, cudaFuncAttributeMaxDynamicSharedMemorySize, DSMEM_SK);
        cudaFuncSetAttribute(fused_gemm_k, cudaFuncAttributeMaxDynamicSharedMemorySize, DSMEM_BIG);
        attr_set = true;
    }

    // 0: weight converts
    conv_weights_k<<<cdiv(6369280, 256), 256>>>(attn_W, Wc, Wg, Wih, Whh, h0, Bf);
    // 1: UGH partials, splitK=4
    skinny_gemm_k<<<dim3(16, 1, 4), 256, DSMEM_SK>>>(bH0, 512, bW1c, 512, UGHP, Bn, 2048, 128);
    // 2: emb + db
    fill_x_k<<<Bn, 256>>>(dec_last_w, emb, db, bX);
    // 3 (profiled slot): fused GEMM (R10 config) + fast-tanh epilogues
    fused_gemm_k<<<dim3(2, YATT + YCPY), 512, DSMEM_BIG>>>(usdx_h, bspn_h, pv_h, Bf, Wcb, bTB, SP, UGHP, attn_b, v_w);
    // 4: softmax + ctx (fp32 enc, bf16 out)
    softmax_ctx_all_k<<<dim3(Bn, 2, 3), 256>>>(SP, usdx_ids, bspn_ids, pv_ids, usdx_h, bspn_h, pv_h, bX);
    // 5: GI partials, splitK=5, Kc=416
    skinny_gemm_k<<<dim3(12, 1, 5), 256, DSMEM_SK>>>(bX, XD, bWIH, XD, GIP, Bn, G3H, 416);
    // 6: GRU cell
    gru_cell_k<<<cdiv(Bn*Hd, 256), 256>>>(GIP, UGHP, bih, bhh, h0, HNEW, bHN);
    // 7: GEN partials, splitK=4
    skinny_gemm_k<<<dim3(cdiv(3000, 128), 1, 4), 256, DSMEM_SK>>>(bHN, 512, bWG, 512, GENP, Bn, Vd, 128);
    // 8: copy scores
    cpraw_k<<<(Bn*TBt)/8, 256>>>(bTB, HNEW, bspn_ids, CPR);
    // 9: final epilogue
    final_k<<<Bn, 256>>>(GENP, Wgb, CPR, nounk, out);
}